// round 7
// baseline (speedup 1.0000x reference)
#include <cuda_runtime.h>

// MaxPool 2x2 stride 2, (16,64,512,512) fp32 -> (16,64,256,256) fp32.
// Persistent single-wave grid-stride variant of the best (R1) layout:
// 1184 blocks (148 SMs x 8 CTAs) x 256 threads, each thread loops over
// output float4s with stride = gridDim*blockDim. Identical coalescing to R1
// (consecutive threads -> consecutive output float4, 4x LDG.128 + STG.128),
// but eliminates ~54 launch waves of CTA setup/teardown. Unroll x2 keeps
// 8 loads in flight per thread.

#define IN_H 512
#define OUT_H 256
#define BC (16 * 64)

#define IN_ROW_F4 128   // 512 floats / 4
#define OUT_ROW_F4 64   // 256 floats / 4
#define TOTAL_OUT_F4 (BC * OUT_H * OUT_ROW_F4)  // 16,777,216

__global__ void maxpool2x2_kernel(const float4* __restrict__ in4,
                                  float4* __restrict__ out4) {
    unsigned stride = gridDim.x * blockDim.x;          // 303,104
    unsigned tid = blockIdx.x * blockDim.x + threadIdx.x;

    // TOTAL_OUT_F4 / stride is not integral; loop with bounds checks on the
    // unrolled pair. stride covers ~55.35 iterations.
    for (unsigned i = tid; i < TOTAL_OUT_F4; i += 2 * stride) {
        unsigned j = i + stride;
        bool has_j = (j < TOTAL_OUT_F4);

        // --- index math for i ---
        unsigned ox4  = i & (OUT_ROW_F4 - 1);
        unsigned rest = i >> 6;
        unsigned oy   = rest & (OUT_H - 1);
        unsigned bc   = rest >> 8;
        unsigned ib0  = bc * (IN_H * IN_ROW_F4) + (oy * 2) * IN_ROW_F4 + ox4 * 2;

        // --- index math for j ---
        unsigned ib1 = 0;
        if (has_j) {
            unsigned ox4j  = j & (OUT_ROW_F4 - 1);
            unsigned restj = j >> 6;
            unsigned oyj   = restj & (OUT_H - 1);
            unsigned bcj   = restj >> 8;
            ib1 = bcj * (IN_H * IN_ROW_F4) + (oyj * 2) * IN_ROW_F4 + ox4j * 2;
        }

        // Front-batch all loads for both outputs (up to 8 LDG.128 in flight).
        float4 a0 = in4[ib0];
        float4 a1 = in4[ib0 + 1];
        float4 a2 = in4[ib0 + IN_ROW_F4];
        float4 a3 = in4[ib0 + IN_ROW_F4 + 1];

        float4 b0, b1, b2, b3;
        if (has_j) {
            b0 = in4[ib1];
            b1 = in4[ib1 + 1];
            b2 = in4[ib1 + IN_ROW_F4];
            b3 = in4[ib1 + IN_ROW_F4 + 1];
        }

        float4 o;
        o.x = fmaxf(fmaxf(a0.x, a0.y), fmaxf(a2.x, a2.y));
        o.y = fmaxf(fmaxf(a0.z, a0.w), fmaxf(a2.z, a2.w));
        o.z = fmaxf(fmaxf(a1.x, a1.y), fmaxf(a3.x, a3.y));
        o.w = fmaxf(fmaxf(a1.z, a1.w), fmaxf(a3.z, a3.w));
        out4[i] = o;

        if (has_j) {
            float4 p;
            p.x = fmaxf(fmaxf(b0.x, b0.y), fmaxf(b2.x, b2.y));
            p.y = fmaxf(fmaxf(b0.z, b0.w), fmaxf(b2.z, b2.w));
            p.z = fmaxf(fmaxf(b1.x, b1.y), fmaxf(b3.x, b3.y));
            p.w = fmaxf(fmaxf(b1.z, b1.w), fmaxf(b3.z, b3.w));
            out4[j] = p;
        }
    }
}

extern "C" void kernel_launch(void* const* d_in, const int* in_sizes, int n_in,
                              void* d_out, int out_size) {
    const float4* in4 = (const float4*)d_in[0];
    float4* out4 = (float4*)d_out;

    const int threads = 256;
    const int blocks = 148 * 8;   // one full wave at 8 CTAs/SM (regs<=32, no smem)

    maxpool2x2_kernel<<<blocks, threads>>>(in4, out4);
}

// round 8
// speedup vs baseline: 1.0989x; 1.0989x over previous
#include <cuda_runtime.h>

// MaxPool 2x2 stride 2, (16,64,512,512) fp32 -> (16,64,256,256) fp32.
// FINAL (R1 layout): DRAM-roofline streaming kernel at the measured
// mixed-stream HBM ceiling — 7283 GB/s, 91.9% of 8TB/s spec, 186.3us.
//
// One thread -> one float4 output (4 pooled values) via 4x coalesced LDG.128
// + 1x STG.128. 65,536 tiny CTAs: the HW CTA rasterizer provides free, deep
// memory-level parallelism across waves (measured better than persistent
// grid-stride, which cost occupancy and serialized loads: 205us).
//
// Explored and rejected (all measured):
//   64B/thread spread loads      -> 188.4us (16 lines/wavefront, L1 70%)
//   perfect-coalesce f2 output   -> 186.8us (neutral)
//   warp-per-row-pair MLP=8      -> 186.8us (neutral)
//   __stcs / __ldcs cache hints  -> 186.9us (neutral; L2 policy not binding)
//   persistent 1-wave grid       -> 204.9us (occ drop + loop serialization)

#define IN_H 512
#define OUT_H 256
#define BC (16 * 64)

#define IN_ROW_F4 128   // 512 floats / 4
#define OUT_ROW_F4 64   // 256 floats / 4

__global__ void maxpool2x2_kernel(const float4* __restrict__ in4,
                                  float4* __restrict__ out4) {
    unsigned tid = blockIdx.x * blockDim.x + threadIdx.x;

    unsigned ox4  = tid & (OUT_ROW_F4 - 1);         // [0, 64)
    unsigned rest = tid >> 6;
    unsigned oy   = rest & (OUT_H - 1);             // [0, 256)
    unsigned bc   = rest >> 8;                      // [0, 1024)

    unsigned ibase = bc * (IN_H * IN_ROW_F4) + (oy * 2) * IN_ROW_F4 + ox4 * 2;

    float4 r0a = in4[ibase];
    float4 r0b = in4[ibase + 1];
    float4 r1a = in4[ibase + IN_ROW_F4];
    float4 r1b = in4[ibase + IN_ROW_F4 + 1];

    float4 o;
    o.x = fmaxf(fmaxf(r0a.x, r0a.y), fmaxf(r1a.x, r1a.y));
    o.y = fmaxf(fmaxf(r0a.z, r0a.w), fmaxf(r1a.z, r1a.w));
    o.z = fmaxf(fmaxf(r0b.x, r0b.y), fmaxf(r1b.x, r1b.y));
    o.w = fmaxf(fmaxf(r0b.z, r0b.w), fmaxf(r1b.z, r1b.w));

    out4[tid] = o;
}

extern "C" void kernel_launch(void* const* d_in, const int* in_sizes, int n_in,
                              void* d_out, int out_size) {
    const float4* in4 = (const float4*)d_in[0];
    float4* out4 = (float4*)d_out;

    const unsigned total = (unsigned)BC * OUT_H * OUT_ROW_F4;  // 16,777,216
    const int threads = 256;
    const unsigned blocks = total / threads;                   // 65,536

    maxpool2x2_kernel<<<blocks, threads>>>(in4, out4);
}

// round 9
// speedup vs baseline: 1.0991x; 1.0002x over previous
#include <cuda_runtime.h>

// MaxPool 2x2 stride 2, (16,64,512,512) fp32 -> (16,64,256,256) fp32.
// R1 layout (best measured: 186.3us, 91.9% of HBM spec) with two micro-tweaks:
//  - 128-thread CTAs (131,072 blocks): finer rasterization grain; R7 showed
//    the HW CTA pipeline is the best latency-hiding engine for this stream,
//    so go finer, not coarser. Global index mapping is byte-identical to R1.
//  - __ldcg loads (L2-only): stream-once data has 0% L1 hit rate by
//    construction; skip the L1 allocation stage.
// One thread -> one float4 output via 4x coalesced LDG.128 + 1x STG.128.

#define IN_H 512
#define OUT_H 256
#define BC (16 * 64)

#define IN_ROW_F4 128   // 512 floats / 4
#define OUT_ROW_F4 64   // 256 floats / 4

__global__ void maxpool2x2_kernel(const float4* __restrict__ in4,
                                  float4* __restrict__ out4) {
    unsigned tid = blockIdx.x * blockDim.x + threadIdx.x;

    unsigned ox4  = tid & (OUT_ROW_F4 - 1);         // [0, 64)
    unsigned rest = tid >> 6;
    unsigned oy   = rest & (OUT_H - 1);             // [0, 256)
    unsigned bc   = rest >> 8;                      // [0, 1024)

    unsigned ibase = bc * (IN_H * IN_ROW_F4) + (oy * 2) * IN_ROW_F4 + ox4 * 2;

    float4 r0a = __ldcg(&in4[ibase]);
    float4 r0b = __ldcg(&in4[ibase + 1]);
    float4 r1a = __ldcg(&in4[ibase + IN_ROW_F4]);
    float4 r1b = __ldcg(&in4[ibase + IN_ROW_F4 + 1]);

    float4 o;
    o.x = fmaxf(fmaxf(r0a.x, r0a.y), fmaxf(r1a.x, r1a.y));
    o.y = fmaxf(fmaxf(r0a.z, r0a.w), fmaxf(r1a.z, r1a.w));
    o.z = fmaxf(fmaxf(r0b.x, r0b.y), fmaxf(r1b.x, r1b.y));
    o.w = fmaxf(fmaxf(r0b.z, r0b.w), fmaxf(r1b.z, r1b.w));

    out4[tid] = o;
}

extern "C" void kernel_launch(void* const* d_in, const int* in_sizes, int n_in,
                              void* d_out, int out_size) {
    const float4* in4 = (const float4*)d_in[0];
    float4* out4 = (float4*)d_out;

    const unsigned total = (unsigned)BC * OUT_H * OUT_ROW_F4;  // 16,777,216
    const int threads = 128;
    const unsigned blocks = total / threads;                   // 131,072

    maxpool2x2_kernel<<<blocks, threads>>>(in4, out4);
}

// round 10
// speedup vs baseline: 1.1006x; 1.0014x over previous
#include <cuda_runtime.h>

// MaxPool 2x2 stride 2, (16,64,512,512) fp32 -> (16,64,256,256) fp32.
// DRAM-ceiling streaming kernel. Measured grain scan (DRAM active %):
//   1 persistent wave: 86.1%  |  256-thr CTAs: 91.5%  |  128-thr CTAs: 92.2%
// -> finer CTA grain monotonically improves DRAM occupancy on this chip
//    (HW rasterizer turnover = free MLP injection). This round: 64-thr CTAs
//    (262,144 blocks, 32 resident CTAs/SM = same 2048 threads, 2x turnover).
// Loads are __ldcg (L2-only; stream-once data never hits in L1).
// One thread -> one float4 output via 4x coalesced LDG.128 + 1x STG.128.

#define IN_H 512
#define OUT_H 256
#define BC (16 * 64)

#define IN_ROW_F4 128   // 512 floats / 4
#define OUT_ROW_F4 64   // 256 floats / 4

__global__ void maxpool2x2_kernel(const float4* __restrict__ in4,
                                  float4* __restrict__ out4) {
    unsigned tid = blockIdx.x * blockDim.x + threadIdx.x;

    unsigned ox4  = tid & (OUT_ROW_F4 - 1);         // [0, 64)
    unsigned rest = tid >> 6;
    unsigned oy   = rest & (OUT_H - 1);             // [0, 256)
    unsigned bc   = rest >> 8;                      // [0, 1024)

    unsigned ibase = bc * (IN_H * IN_ROW_F4) + (oy * 2) * IN_ROW_F4 + ox4 * 2;

    float4 r0a = __ldcg(&in4[ibase]);
    float4 r0b = __ldcg(&in4[ibase + 1]);
    float4 r1a = __ldcg(&in4[ibase + IN_ROW_F4]);
    float4 r1b = __ldcg(&in4[ibase + IN_ROW_F4 + 1]);

    float4 o;
    o.x = fmaxf(fmaxf(r0a.x, r0a.y), fmaxf(r1a.x, r1a.y));
    o.y = fmaxf(fmaxf(r0a.z, r0a.w), fmaxf(r1a.z, r1a.w));
    o.z = fmaxf(fmaxf(r0b.x, r0b.y), fmaxf(r1b.x, r1b.y));
    o.w = fmaxf(fmaxf(r0b.z, r0b.w), fmaxf(r1b.z, r1b.w));

    out4[tid] = o;
}

extern "C" void kernel_launch(void* const* d_in, const int* in_sizes, int n_in,
                              void* d_out, int out_size) {
    const float4* in4 = (const float4*)d_in[0];
    float4* out4 = (float4*)d_out;

    const unsigned total = (unsigned)BC * OUT_H * OUT_ROW_F4;  // 16,777,216
    const int threads = 64;
    const unsigned blocks = total / threads;                   // 262,144

    maxpool2x2_kernel<<<blocks, threads>>>(in4, out4);
}